// round 1
// baseline (speedup 1.0000x reference)
#include <cuda_runtime.h>

#define Bc   2
#define Tc   2048
#define Cc   2048
#define NH   16
#define NKV  2
#define DH   128
#define Mrows (Bc*Tc)          // 4096
#define KVC  (NKV*DH)          // 256

#define QPAD 132
#define PPAD 68
#define ATTN_SMEM_BYTES ((3*64*QPAD + 64*PPAD)*4)   // 118784 bytes

// ---------------- scratch (allocation-free rule: __device__ globals) --------
__device__ float g_q[(size_t)Mrows * Cc];
__device__ float g_k[(size_t)Mrows * KVC];
__device__ float g_v[(size_t)Mrows * KVC];
__device__ float g_y[(size_t)Mrows * Cc];

// ---------------- 128x128x8 SIMT fp32 GEMM ---------------------------------
// C[M,N] = A[M,K] @ B[K,N], all row-major. M%128==0, N%128==0, K%8==0.
__global__ __launch_bounds__(256) void sgemm128(const float* __restrict__ A,
                                                const float* __restrict__ B,
                                                float* __restrict__ C,
                                                int M, int N, int K)
{
    __shared__ float As[8][128];
    __shared__ float Bs[8][128];

    const int bm = blockIdx.y * 128;
    const int bn = blockIdx.x * 128;
    const int tid = threadIdx.x;
    const int tx = tid & 15, ty = tid >> 4;

    // A tile loader: 128 rows x 8 cols; 2 threads per row, float4 each
    const int arow = tid >> 1, acol = (tid & 1) * 4;
    // B tile loader: 8 rows x 128 cols; 32 threads per row, float4 each
    const int brow = tid >> 5, bcol = (tid & 31) * 4;

    float acc[8][8];
#pragma unroll
    for (int i = 0; i < 8; i++)
#pragma unroll
        for (int j = 0; j < 8; j++) acc[i][j] = 0.f;

    for (int k0 = 0; k0 < K; k0 += 8) {
        float4 av = *(const float4*)(A + (size_t)(bm + arow) * K + k0 + acol);
        As[acol + 0][arow] = av.x;
        As[acol + 1][arow] = av.y;
        As[acol + 2][arow] = av.z;
        As[acol + 3][arow] = av.w;
        *(float4*)(&Bs[brow][bcol]) =
            *(const float4*)(B + (size_t)(k0 + brow) * N + bn + bcol);
        __syncthreads();

#pragma unroll
        for (int kk = 0; kk < 8; kk++) {
            float a[8], b[8];
            *(float4*)(a)     = *(const float4*)(&As[kk][ty * 8]);
            *(float4*)(a + 4) = *(const float4*)(&As[kk][ty * 8 + 4]);
            *(float4*)(b)     = *(const float4*)(&Bs[kk][tx * 8]);
            *(float4*)(b + 4) = *(const float4*)(&Bs[kk][tx * 8 + 4]);
#pragma unroll
            for (int i = 0; i < 8; i++)
#pragma unroll
                for (int j = 0; j < 8; j++) acc[i][j] += a[i] * b[j];
        }
        __syncthreads();
    }

#pragma unroll
    for (int i = 0; i < 8; i++) {
        float4 v0 = make_float4(acc[i][0], acc[i][1], acc[i][2], acc[i][3]);
        float4 v1 = make_float4(acc[i][4], acc[i][5], acc[i][6], acc[i][7]);
        size_t base = (size_t)(bm + ty * 8 + i) * N + bn + tx * 8;
        *(float4*)(C + base)     = v0;
        *(float4*)(C + base + 4) = v1;
    }
}

// ---------------- causal GQA flash attention -------------------------------
// grid: (T/64, NH, B), 256 threads.
// Q layout: g_q[(b*T+t)*C + h*D + d]   (head-major columns after reshape)
// K/V:      g_k[(b*T+t)*KVC + g*D + d]
// Output:   g_y[(b*T+t)*C + h*D + d]
__global__ __launch_bounds__(256) void attn_kernel()
{
    extern __shared__ float sm[];
    float* Qs = sm;                    // [64][QPAD]
    float* Ks = Qs + 64 * QPAD;        // [64][QPAD]
    float* Vs = Ks + 64 * QPAD;        // [64][QPAD]
    float* Ps = Vs + 64 * QPAD;        // [64][PPAD]

    const int qt = blockIdx.x;
    const int h  = blockIdx.y;
    const int b  = blockIdx.z;
    const int g  = h / (NH / NKV);
    const int tid = threadIdx.x;
    const int tx = tid & 15, ty = tid >> 4;
    const int q0 = qt * 64;
    const float scale = 0.08838834764831843f;   // 1/sqrt(128)

    // load + pre-scale Q tile (64 x 128)
    for (int i = tid; i < 64 * 32; i += 256) {
        int r = i >> 5, c4 = (i & 31) * 4;
        float4 v = *(const float4*)(g_q + (size_t)(b * Tc + q0 + r) * Cc + h * DH + c4);
        v.x *= scale; v.y *= scale; v.z *= scale; v.w *= scale;
        *(float4*)(Qs + r * QPAD + c4) = v;
    }

    float o[4][8];
    float m[4], l[4];
#pragma unroll
    for (int i = 0; i < 4; i++) {
        m[i] = -1e30f; l[i] = 0.f;
#pragma unroll
        for (int j = 0; j < 8; j++) o[i][j] = 0.f;
    }

    for (int jt = 0; jt <= qt; jt++) {
        const int k0 = jt * 64;
        __syncthreads();   // protect Ks/Vs/Ps from prior-iteration readers; covers Q stores on iter 0
        for (int i = tid; i < 64 * 32; i += 256) {
            int r = i >> 5, c4 = (i & 31) * 4;
            size_t base = (size_t)(b * Tc + k0 + r) * KVC + g * DH + c4;
            *(float4*)(Ks + r * QPAD + c4) = *(const float4*)(g_k + base);
            *(float4*)(Vs + r * QPAD + c4) = *(const float4*)(g_v + base);
        }
        __syncthreads();

        // S = Qs @ Ks^T  (64x64, 4x4 per thread)
        float s[4][4];
#pragma unroll
        for (int i = 0; i < 4; i++)
#pragma unroll
            for (int j = 0; j < 4; j++) s[i][j] = 0.f;

        for (int d = 0; d < DH; d += 4) {
            float4 a4[4], b4[4];
#pragma unroll
            for (int i = 0; i < 4; i++) a4[i] = *(const float4*)(Qs + (ty * 4 + i) * QPAD + d);
#pragma unroll
            for (int j = 0; j < 4; j++) b4[j] = *(const float4*)(Ks + (tx * 4 + j) * QPAD + d);
#pragma unroll
            for (int i = 0; i < 4; i++)
#pragma unroll
                for (int j = 0; j < 4; j++)
                    s[i][j] += a4[i].x * b4[j].x + a4[i].y * b4[j].y
                             + a4[i].z * b4[j].z + a4[i].w * b4[j].w;
        }

        if (jt == qt) {
#pragma unroll
            for (int i = 0; i < 4; i++)
#pragma unroll
                for (int j = 0; j < 4; j++)
                    if (k0 + tx * 4 + j > q0 + ty * 4 + i) s[i][j] = -1e30f;
        }

        // online softmax (row reductions across the 16 tx threads of a half-warp)
#pragma unroll
        for (int i = 0; i < 4; i++) {
            float rmax = fmaxf(fmaxf(s[i][0], s[i][1]), fmaxf(s[i][2], s[i][3]));
            rmax = fmaxf(rmax, __shfl_xor_sync(0xffffffffu, rmax, 1, 16));
            rmax = fmaxf(rmax, __shfl_xor_sync(0xffffffffu, rmax, 2, 16));
            rmax = fmaxf(rmax, __shfl_xor_sync(0xffffffffu, rmax, 4, 16));
            rmax = fmaxf(rmax, __shfl_xor_sync(0xffffffffu, rmax, 8, 16));
            float mn = fmaxf(m[i], rmax);
            float alpha = __expf(m[i] - mn);
            float rsum = 0.f;
#pragma unroll
            for (int j = 0; j < 4; j++) { s[i][j] = __expf(s[i][j] - mn); rsum += s[i][j]; }
            rsum += __shfl_xor_sync(0xffffffffu, rsum, 1, 16);
            rsum += __shfl_xor_sync(0xffffffffu, rsum, 2, 16);
            rsum += __shfl_xor_sync(0xffffffffu, rsum, 4, 16);
            rsum += __shfl_xor_sync(0xffffffffu, rsum, 8, 16);
            l[i] = l[i] * alpha + rsum;
            m[i] = mn;
#pragma unroll
            for (int j = 0; j < 8; j++) o[i][j] *= alpha;
            *(float4*)(Ps + (ty * 4 + i) * PPAD + tx * 4) =
                make_float4(s[i][0], s[i][1], s[i][2], s[i][3]);
        }
        __syncthreads();

        // O += P @ V   (64x64 @ 64x128; each thread 4 rows x 8 cols)
#pragma unroll 4
        for (int kc = 0; kc < 64; kc++) {
            float4 v0 = *(const float4*)(Vs + kc * QPAD + tx * 8);
            float4 v1 = *(const float4*)(Vs + kc * QPAD + tx * 8 + 4);
#pragma unroll
            for (int i = 0; i < 4; i++) {
                float a = Ps[(ty * 4 + i) * PPAD + kc];
                o[i][0] += a * v0.x; o[i][1] += a * v0.y;
                o[i][2] += a * v0.z; o[i][3] += a * v0.w;
                o[i][4] += a * v1.x; o[i][5] += a * v1.y;
                o[i][6] += a * v1.z; o[i][7] += a * v1.w;
            }
        }
    }

#pragma unroll
    for (int i = 0; i < 4; i++) {
        float inv = 1.f / l[i];
        float4 v0 = make_float4(o[i][0] * inv, o[i][1] * inv, o[i][2] * inv, o[i][3] * inv);
        float4 v1 = make_float4(o[i][4] * inv, o[i][5] * inv, o[i][6] * inv, o[i][7] * inv);
        size_t base = (size_t)(b * Tc + q0 + ty * 4 + i) * Cc + h * DH + tx * 8;
        *(float4*)(g_y + base)     = v0;
        *(float4*)(g_y + base + 4) = v1;
    }
}

// ---------------- launch ----------------------------------------------------
extern "C" void kernel_launch(void* const* d_in, const int* in_sizes, int n_in,
                              void* d_out, int out_size)
{
    const float* x  = (const float*)d_in[0];
    const float* Wq = (const float*)d_in[1];
    const float* Wk = (const float*)d_in[2];
    const float* Wv = (const float*)d_in[3];
    const float* Wo = (const float*)d_in[4];
    float* out = (float*)d_out;

    static bool inited = false;
    static float *qp, *kp, *vp, *yp;
    if (!inited) {
        cudaGetSymbolAddress((void**)&qp, g_q);
        cudaGetSymbolAddress((void**)&kp, g_k);
        cudaGetSymbolAddress((void**)&vp, g_v);
        cudaGetSymbolAddress((void**)&yp, g_y);
        cudaFuncSetAttribute(attn_kernel,
                             cudaFuncAttributeMaxDynamicSharedMemorySize,
                             ATTN_SMEM_BYTES);
        inited = true;
    }

    dim3 blk(256);
    sgemm128<<<dim3(Cc / 128, Mrows / 128), blk>>>(x, Wq, qp, Mrows, Cc, Cc);
    sgemm128<<<dim3(KVC / 128, Mrows / 128), blk>>>(x, Wk, kp, Mrows, KVC, Cc);
    sgemm128<<<dim3(KVC / 128, Mrows / 128), blk>>>(x, Wv, vp, Mrows, KVC, Cc);
    attn_kernel<<<dim3(Tc / 64, NH, Bc), blk, ATTN_SMEM_BYTES>>>();
    sgemm128<<<dim3(Cc / 128, Mrows / 128), blk>>>(yp, Wo, out, Mrows, Cc, Cc);
}

// round 3
// speedup vs baseline: 1.6336x; 1.6336x over previous
#include <cuda_runtime.h>
#include <cstdint>

#define Bc   2
#define Tc   2048
#define Cc   2048
#define NH   16
#define NKV  2
#define DH   128
#define Mrows (Bc*Tc)          // 4096
#define KVW  512               // packed K|V width

#define QPAD 132
#define PPAD 68
#define ATTN_SMEM_BYTES ((3*64*QPAD + 64*PPAD)*4)   // 118784 bytes

// ---------------- scratch (allocation-free rule: __device__ globals) --------
__device__ float g_xr[(size_t)Mrows * Cc];    // RN-tf32 rounded x
__device__ float g_q [(size_t)Mrows * Cc];
__device__ float g_kv[(size_t)Mrows * KVW];   // [.. , 0:256)=K heads, [256:512)=V heads
__device__ float g_yr[(size_t)Mrows * Cc];    // attention out, RN-tf32 rounded
__device__ float g_wqt [(size_t)Cc  * Cc];    // Wq^T  [N=2048][K=2048]
__device__ float g_wkvt[(size_t)KVW * Cc];    // [Wk^T ; Wv^T]  [512][2048]
__device__ float g_wot [(size_t)Cc  * Cc];    // Wo^T

__device__ __forceinline__ float rn_tf32(float v) {
    uint32_t u;
    asm("cvt.rna.tf32.f32 %0, %1;" : "=r"(u) : "f"(v));
    return __uint_as_float(u);
}

__device__ __forceinline__ void mma_tf32(float* c, const uint32_t* a, const uint32_t* b) {
    asm volatile(
        "mma.sync.aligned.m16n8k8.row.col.f32.tf32.tf32.f32 "
        "{%0,%1,%2,%3}, {%4,%5,%6,%7}, {%8,%9}, {%0,%1,%2,%3};"
        : "+f"(c[0]), "+f"(c[1]), "+f"(c[2]), "+f"(c[3])
        : "r"(a[0]), "r"(a[1]), "r"(a[2]), "r"(a[3]), "r"(b[0]), "r"(b[1]));
}

// =================== tf32 mma.sync GEMM =====================================
// C[M,N] = A[M,K] @ Bt[N,K]^T. A,Bt row-major, RN-tf32-rounded fp32.
// CTA tile 128x128, 8 warps (2x4), warp tile 64x32, K-chunk 16, double buffer.
#define KC 16
#define KP 20     // smem row stride (floats): 16B-aligned, conflict-free

__global__ __launch_bounds__(256) void gemm_mma(const float* __restrict__ A,
                                                const float* __restrict__ Bt,
                                                float* __restrict__ C,
                                                int M, int N, int K)
{
    __shared__ float As[2][128 * KP];
    __shared__ float Bs[2][128 * KP];

    const int tid  = threadIdx.x;
    const int wid  = tid >> 5, lane = tid & 31;
    const int lr   = lane >> 2, lc = lane & 3;
    const int wm   = (wid & 1) * 64;       // warp row offset in CTA tile
    const int wn   = (wid >> 1) * 32;      // warp col offset
    const int bm   = blockIdx.y * 128;
    const int bn   = blockIdx.x * 128;

    // tile fill mapping: 512 float4 per tile, 2 per thread
    const int r0 = tid >> 2,        c40 = (tid & 3) << 2;
    const int r1 = (tid + 256) >> 2, c41 = ((tid + 256) & 3) << 2;

    float acc[4][4][4];
#pragma unroll
    for (int i = 0; i < 4; i++)
#pragma unroll
        for (int j = 0; j < 4; j++)
#pragma unroll
            for (int r = 0; r < 4; r++) acc[i][j][r] = 0.f;

    const int nc = K / KC;

    // preload chunk 0
    float4 pa0 = *(const float4*)(A  + (size_t)(bm + r0) * K + c40);
    float4 pa1 = *(const float4*)(A  + (size_t)(bm + r1) * K + c41);
    float4 pb0 = *(const float4*)(Bt + (size_t)(bn + r0) * K + c40);
    float4 pb1 = *(const float4*)(Bt + (size_t)(bn + r1) * K + c41);
    *(float4*)(&As[0][r0 * KP + c40]) = pa0;
    *(float4*)(&As[0][r1 * KP + c41]) = pa1;
    *(float4*)(&Bs[0][r0 * KP + c40]) = pb0;
    *(float4*)(&Bs[0][r1 * KP + c41]) = pb1;
    __syncthreads();

    for (int c = 0; c < nc; c++) {
        const int buf = c & 1;
        if (c + 1 < nc) {
            const int kb = (c + 1) * KC;
            pa0 = *(const float4*)(A  + (size_t)(bm + r0) * K + kb + c40);
            pa1 = *(const float4*)(A  + (size_t)(bm + r1) * K + kb + c41);
            pb0 = *(const float4*)(Bt + (size_t)(bn + r0) * K + kb + c40);
            pb1 = *(const float4*)(Bt + (size_t)(bn + r1) * K + kb + c41);
        }

#pragma unroll
        for (int ks = 0; ks < 2; ks++) {
            const int k0 = ks * 8;
            uint32_t af[4][4], bf[4][2];
#pragma unroll
            for (int mf = 0; mf < 4; mf++) {
                const float* p = &As[buf][(wm + mf * 16 + lr) * KP + k0 + lc];
                af[mf][0] = __float_as_uint(p[0]);
                af[mf][1] = __float_as_uint(p[8 * KP]);
                af[mf][2] = __float_as_uint(p[4]);
                af[mf][3] = __float_as_uint(p[8 * KP + 4]);
            }
#pragma unroll
            for (int nf = 0; nf < 4; nf++) {
                const float* p = &Bs[buf][(wn + nf * 8 + lr) * KP + k0 + lc];
                bf[nf][0] = __float_as_uint(p[0]);
                bf[nf][1] = __float_as_uint(p[4]);
            }
#pragma unroll
            for (int mf = 0; mf < 4; mf++)
#pragma unroll
                for (int nf = 0; nf < 4; nf++)
                    mma_tf32(acc[mf][nf], af[mf], bf[nf]);
        }

        if (c + 1 < nc) {
            const int nb = buf ^ 1;
            *(float4*)(&As[nb][r0 * KP + c40]) = pa0;
            *(float4*)(&As[nb][r1 * KP + c41]) = pa1;
            *(float4*)(&Bs[nb][r0 * KP + c40]) = pb0;
            *(float4*)(&Bs[nb][r1 * KP + c41]) = pb1;
        }
        __syncthreads();
    }

    // epilogue: c0,c1 -> (row, col..col+1); c2,c3 -> (row+8, ...)
#pragma unroll
    for (int mf = 0; mf < 4; mf++) {
#pragma unroll
        for (int nf = 0; nf < 4; nf++) {
            const int row = bm + wm + mf * 16 + lr;
            const int col = bn + wn + nf * 8 + lc * 2;
            *(float2*)(C + (size_t)row * N + col) =
                make_float2(acc[mf][nf][0], acc[mf][nf][1]);
            *(float2*)(C + (size_t)(row + 8) * N + col) =
                make_float2(acc[mf][nf][2], acc[mf][nf][3]);
        }
    }
}

// =================== aux kernels ============================================
// out[n][k] = rn_tf32(in[k][n]); in is [K][N] row-major.
__global__ void transpose_rn(const float* __restrict__ in, float* __restrict__ out,
                             int K, int N)
{
    __shared__ float t[32][33];
    const int n0 = blockIdx.x * 32, k0 = blockIdx.y * 32;
    const int x = threadIdx.x, y = threadIdx.y;
    for (int i = y; i < 32; i += 8)
        t[i][x] = in[(size_t)(k0 + i) * N + n0 + x];
    __syncthreads();
    for (int i = y; i < 32; i += 8)
        out[(size_t)(n0 + i) * K + k0 + x] = rn_tf32(t[x][i]);
}

__global__ void cvt_rn_vec(const float4* __restrict__ in, float4* __restrict__ out, int n4)
{
    int i = blockIdx.x * blockDim.x + threadIdx.x;
    if (i < n4) {
        float4 v = in[i];
        v.x = rn_tf32(v.x); v.y = rn_tf32(v.y); v.z = rn_tf32(v.z); v.w = rn_tf32(v.w);
        out[i] = v;
    }
}

// ---------------- causal GQA flash attention (fp32 SIMT) --------------------
__global__ __launch_bounds__(256) void attn_kernel()
{
    extern __shared__ float smf[];
    float* Qs = smf;
    float* Ks = Qs + 64 * QPAD;
    float* Vs = Ks + 64 * QPAD;
    float* Ps = Vs + 64 * QPAD;

    const int qt = blockIdx.x;
    const int h  = blockIdx.y;
    const int b  = blockIdx.z;
    const int g  = h / (NH / NKV);
    const int tid = threadIdx.x;
    const int tx = tid & 15, ty = tid >> 4;
    const int q0 = qt * 64;
    const float scale = 0.08838834764831843f;

    for (int i = tid; i < 64 * 32; i += 256) {
        int r = i >> 5, c4 = (i & 31) * 4;
        float4 v = *(const float4*)(g_q + (size_t)(b * Tc + q0 + r) * Cc + h * DH + c4);
        v.x *= scale; v.y *= scale; v.z *= scale; v.w *= scale;
        *(float4*)(Qs + r * QPAD + c4) = v;
    }

    float o[4][8];
    float m[4], l[4];
#pragma unroll
    for (int i = 0; i < 4; i++) {
        m[i] = -1e30f; l[i] = 0.f;
#pragma unroll
        for (int j = 0; j < 8; j++) o[i][j] = 0.f;
    }

    for (int jt = 0; jt <= qt; jt++) {
        const int k0 = jt * 64;
        __syncthreads();
        for (int i = tid; i < 64 * 32; i += 256) {
            int r = i >> 5, c4 = (i & 31) * 4;
            size_t base = (size_t)(b * Tc + k0 + r) * KVW + g * DH + c4;
            *(float4*)(Ks + r * QPAD + c4) = *(const float4*)(g_kv + base);
            *(float4*)(Vs + r * QPAD + c4) = *(const float4*)(g_kv + base + 256);
        }
        __syncthreads();

        float s[4][4];
#pragma unroll
        for (int i = 0; i < 4; i++)
#pragma unroll
            for (int j = 0; j < 4; j++) s[i][j] = 0.f;

        for (int d = 0; d < DH; d += 4) {
            float4 a4[4], b4[4];
#pragma unroll
            for (int i = 0; i < 4; i++) a4[i] = *(const float4*)(Qs + (ty * 4 + i) * QPAD + d);
#pragma unroll
            for (int j = 0; j < 4; j++) b4[j] = *(const float4*)(Ks + (tx * 4 + j) * QPAD + d);
#pragma unroll
            for (int i = 0; i < 4; i++)
#pragma unroll
                for (int j = 0; j < 4; j++)
                    s[i][j] += a4[i].x * b4[j].x + a4[i].y * b4[j].y
                             + a4[i].z * b4[j].z + a4[i].w * b4[j].w;
        }

        if (jt == qt) {
#pragma unroll
            for (int i = 0; i < 4; i++)
#pragma unroll
                for (int j = 0; j < 4; j++)
                    if (k0 + tx * 4 + j > q0 + ty * 4 + i) s[i][j] = -1e30f;
        }

#pragma unroll
        for (int i = 0; i < 4; i++) {
            float rmax = fmaxf(fmaxf(s[i][0], s[i][1]), fmaxf(s[i][2], s[i][3]));
            rmax = fmaxf(rmax, __shfl_xor_sync(0xffffffffu, rmax, 1, 16));
            rmax = fmaxf(rmax, __shfl_xor_sync(0xffffffffu, rmax, 2, 16));
            rmax = fmaxf(rmax, __shfl_xor_sync(0xffffffffu, rmax, 4, 16));
            rmax = fmaxf(rmax, __shfl_xor_sync(0xffffffffu, rmax, 8, 16));
            float mn = fmaxf(m[i], rmax);
            float alpha = __expf(m[i] - mn);
            float rsum = 0.f;
#pragma unroll
            for (int j = 0; j < 4; j++) { s[i][j] = __expf(s[i][j] - mn); rsum += s[i][j]; }
            rsum += __shfl_xor_sync(0xffffffffu, rsum, 1, 16);
            rsum += __shfl_xor_sync(0xffffffffu, rsum, 2, 16);
            rsum += __shfl_xor_sync(0xffffffffu, rsum, 4, 16);
            rsum += __shfl_xor_sync(0xffffffffu, rsum, 8, 16);
            l[i] = l[i] * alpha + rsum;
            m[i] = mn;
#pragma unroll
            for (int j = 0; j < 8; j++) o[i][j] *= alpha;
            *(float4*)(Ps + (ty * 4 + i) * PPAD + tx * 4) =
                make_float4(s[i][0], s[i][1], s[i][2], s[i][3]);
        }
        __syncthreads();

#pragma unroll 4
        for (int kc = 0; kc < 64; kc++) {
            float4 v0 = *(const float4*)(Vs + kc * QPAD + tx * 8);
            float4 v1 = *(const float4*)(Vs + kc * QPAD + tx * 8 + 4);
#pragma unroll
            for (int i = 0; i < 4; i++) {
                float a = Ps[(ty * 4 + i) * PPAD + kc];
                o[i][0] += a * v0.x; o[i][1] += a * v0.y;
                o[i][2] += a * v0.z; o[i][3] += a * v0.w;
                o[i][4] += a * v1.x; o[i][5] += a * v1.y;
                o[i][6] += a * v1.z; o[i][7] += a * v1.w;
            }
        }
    }

#pragma unroll
    for (int i = 0; i < 4; i++) {
        float inv = 1.f / l[i];
        float4 v0 = make_float4(rn_tf32(o[i][0] * inv), rn_tf32(o[i][1] * inv),
                                rn_tf32(o[i][2] * inv), rn_tf32(o[i][3] * inv));
        float4 v1 = make_float4(rn_tf32(o[i][4] * inv), rn_tf32(o[i][5] * inv),
                                rn_tf32(o[i][6] * inv), rn_tf32(o[i][7] * inv));
        size_t base = (size_t)(b * Tc + q0 + ty * 4 + i) * Cc + h * DH + tx * 8;
        *(float4*)(g_yr + base)     = v0;
        *(float4*)(g_yr + base + 4) = v1;
    }
}

// =================== host side ==============================================
extern "C" void kernel_launch(void* const* d_in, const int* in_sizes, int n_in,
                              void* d_out, int out_size)
{
    const float* x  = (const float*)d_in[0];
    const float* Wq = (const float*)d_in[1];
    const float* Wk = (const float*)d_in[2];
    const float* Wv = (const float*)d_in[3];
    const float* Wo = (const float*)d_in[4];
    float* out = (float*)d_out;

    static bool inited = false;
    static float *xr, *qp, *kvp, *yp, *wqt, *wkvt, *wot;
    if (!inited) {
        cudaGetSymbolAddress((void**)&xr,   g_xr);
        cudaGetSymbolAddress((void**)&qp,   g_q);
        cudaGetSymbolAddress((void**)&kvp,  g_kv);
        cudaGetSymbolAddress((void**)&yp,   g_yr);
        cudaGetSymbolAddress((void**)&wqt,  g_wqt);
        cudaGetSymbolAddress((void**)&wkvt, g_wkvt);
        cudaGetSymbolAddress((void**)&wot,  g_wot);
        cudaFuncSetAttribute(attn_kernel, cudaFuncAttributeMaxDynamicSharedMemorySize,
                             ATTN_SMEM_BYTES);
        inited = true;
    }

    // 1) RN-round x
    cvt_rn_vec<<<(Mrows * Cc / 4 + 255) / 256, 256>>>((const float4*)x, (float4*)xr,
                                                      Mrows * Cc / 4);
    // 2) transpose + RN-round weights
    dim3 tb(32, 8);
    transpose_rn<<<dim3(Cc / 32,  Cc / 32), tb>>>(Wq, wqt, Cc, Cc);
    transpose_rn<<<dim3(256 / 32, Cc / 32), tb>>>(Wk, wkvt,            Cc, 256);
    transpose_rn<<<dim3(256 / 32, Cc / 32), tb>>>(Wv, wkvt + 256 * Cc, Cc, 256);
    transpose_rn<<<dim3(Cc / 32,  Cc / 32), tb>>>(Wo, wot, Cc, Cc);

    // 3) projections (tf32 mma.sync)
    gemm_mma<<<dim3(Cc / 128,  Mrows / 128), 256>>>(xr, wqt,  qp,  Mrows, Cc,  Cc);
    gemm_mma<<<dim3(KVW / 128, Mrows / 128), 256>>>(xr, wkvt, kvp, Mrows, KVW, Cc);

    // 4) attention
    attn_kernel<<<dim3(Tc / 64, NH, Bc), 256, ATTN_SMEM_BYTES>>>();

    // 5) output projection
    gemm_mma<<<dim3(Cc / 128, Mrows / 128), 256>>>(yp, wot, out, Mrows, Cc, Cc);
}

// round 4
// speedup vs baseline: 4.3537x; 2.6651x over previous
#include <cuda_runtime.h>
#include <cstdint>

#define Bc   2
#define Tc   2048
#define Cc   2048
#define NH   16
#define NKV  2
#define DH   128
#define Mrows (Bc*Tc)          // 4096
#define QKVW 2560              // q(2048) | k(256) | v(256)

// ---------------- scratch (allocation-free rule: __device__ globals) --------
__device__ float g_xr  [(size_t)Mrows * Cc];     // RN-tf32 rounded x
__device__ float g_qkv [(size_t)Mrows * QKVW];   // fused projections (rounded)
__device__ float g_yr  [(size_t)Mrows * Cc];     // attention out (rounded)
__device__ float g_wqkvt[(size_t)QKVW * Cc];     // [Wq^T ; Wk^T ; Wv^T]
__device__ float g_wot [(size_t)Cc * Cc];        // Wo^T

__device__ __forceinline__ float rn_tf32(float v) {
    uint32_t u;
    asm("cvt.rna.tf32.f32 %0, %1;" : "=r"(u) : "f"(v));
    return __uint_as_float(u);
}
__device__ __forceinline__ float ex2(float x) {
    float y; asm("ex2.approx.f32 %0, %1;" : "=f"(y) : "f"(x)); return y;
}
__device__ __forceinline__ uint32_t smem_to_u32(const void* p) {
    uint32_t a;
    asm("{ .reg .u64 t; cvta.to.shared.u64 t, %1; cvt.u32.u64 %0, t; }"
        : "=r"(a) : "l"(p));
    return a;
}
__device__ __forceinline__ void mma_tf32(float* c, const uint32_t* a, const uint32_t* b) {
    asm volatile(
        "mma.sync.aligned.m16n8k8.row.col.f32.tf32.tf32.f32 "
        "{%0,%1,%2,%3}, {%4,%5,%6,%7}, {%8,%9}, {%0,%1,%2,%3};"
        : "+f"(c[0]), "+f"(c[1]), "+f"(c[2]), "+f"(c[3])
        : "r"(a[0]), "r"(a[1]), "r"(a[2]), "r"(a[3]), "r"(b[0]), "r"(b[1]));
}
#define CP_ASYNC16(sm, gp) \
    asm volatile("cp.async.cg.shared.global [%0], [%1], 16;" :: "r"(sm), "l"(gp))
#define CP_COMMIT asm volatile("cp.async.commit_group;" ::: "memory")
#define CP_WAIT1  asm volatile("cp.async.wait_group 1;"  ::: "memory")

// =================== tf32 mma.sync GEMM =====================================
// C[M,N] = A[M,K] @ Bt[N,K]^T. A,Bt row-major, RN-tf32-rounded fp32.
#define KC 16
#define KP 20

__global__ __launch_bounds__(256) void gemm_mma(const float* __restrict__ A,
                                                const float* __restrict__ Bt,
                                                float* __restrict__ C,
                                                int M, int N, int K, int rnd)
{
    __shared__ float As[2][128 * KP];
    __shared__ float Bs[2][128 * KP];

    const int tid  = threadIdx.x;
    const int wid  = tid >> 5, lane = tid & 31;
    const int lr   = lane >> 2, lc = lane & 3;
    const int wm   = (wid & 1) * 64;
    const int wn   = (wid >> 1) * 32;
    const int bm   = blockIdx.y * 128;
    const int bn   = blockIdx.x * 128;

    const int r0 = tid >> 2,         c40 = (tid & 3) << 2;
    const int r1 = (tid + 256) >> 2, c41 = ((tid + 256) & 3) << 2;

    float acc[4][4][4];
#pragma unroll
    for (int i = 0; i < 4; i++)
#pragma unroll
        for (int j = 0; j < 4; j++)
#pragma unroll
            for (int r = 0; r < 4; r++) acc[i][j][r] = 0.f;

    const int nc = K / KC;

    float4 pa0 = *(const float4*)(A  + (size_t)(bm + r0) * K + c40);
    float4 pa1 = *(const float4*)(A  + (size_t)(bm + r1) * K + c41);
    float4 pb0 = *(const float4*)(Bt + (size_t)(bn + r0) * K + c40);
    float4 pb1 = *(const float4*)(Bt + (size_t)(bn + r1) * K + c41);
    *(float4*)(&As[0][r0 * KP + c40]) = pa0;
    *(float4*)(&As[0][r1 * KP + c41]) = pa1;
    *(float4*)(&Bs[0][r0 * KP + c40]) = pb0;
    *(float4*)(&Bs[0][r1 * KP + c41]) = pb1;
    __syncthreads();

    for (int c = 0; c < nc; c++) {
        const int buf = c & 1;
        if (c + 1 < nc) {
            const int kb = (c + 1) * KC;
            pa0 = *(const float4*)(A  + (size_t)(bm + r0) * K + kb + c40);
            pa1 = *(const float4*)(A  + (size_t)(bm + r1) * K + kb + c41);
            pb0 = *(const float4*)(Bt + (size_t)(bn + r0) * K + kb + c40);
            pb1 = *(const float4*)(Bt + (size_t)(bn + r1) * K + kb + c41);
        }

#pragma unroll
        for (int ks = 0; ks < 2; ks++) {
            const int k0 = ks * 8;
            uint32_t af[4][4], bf[4][2];
#pragma unroll
            for (int mf = 0; mf < 4; mf++) {
                const float* p = &As[buf][(wm + mf * 16 + lr) * KP + k0 + lc];
                af[mf][0] = __float_as_uint(p[0]);
                af[mf][1] = __float_as_uint(p[8 * KP]);
                af[mf][2] = __float_as_uint(p[4]);
                af[mf][3] = __float_as_uint(p[8 * KP + 4]);
            }
#pragma unroll
            for (int nf = 0; nf < 4; nf++) {
                const float* p = &Bs[buf][(wn + nf * 8 + lr) * KP + k0 + lc];
                bf[nf][0] = __float_as_uint(p[0]);
                bf[nf][1] = __float_as_uint(p[4]);
            }
#pragma unroll
            for (int mf = 0; mf < 4; mf++)
#pragma unroll
                for (int nf = 0; nf < 4; nf++)
                    mma_tf32(acc[mf][nf], af[mf], bf[nf]);
        }

        if (c + 1 < nc) {
            const int nb = buf ^ 1;
            *(float4*)(&As[nb][r0 * KP + c40]) = pa0;
            *(float4*)(&As[nb][r1 * KP + c41]) = pa1;
            *(float4*)(&Bs[nb][r0 * KP + c40]) = pb0;
            *(float4*)(&Bs[nb][r1 * KP + c41]) = pb1;
        }
        __syncthreads();
    }

#pragma unroll
    for (int mf = 0; mf < 4; mf++) {
#pragma unroll
        for (int nf = 0; nf < 4; nf++) {
            const int row = bm + wm + mf * 16 + lr;
            const int col = bn + wn + nf * 8 + lc * 2;
            float v0 = acc[mf][nf][0], v1 = acc[mf][nf][1];
            float v2 = acc[mf][nf][2], v3 = acc[mf][nf][3];
            if (rnd) { v0 = rn_tf32(v0); v1 = rn_tf32(v1);
                       v2 = rn_tf32(v2); v3 = rn_tf32(v3); }
            *(float2*)(C + (size_t)row * N + col)       = make_float2(v0, v1);
            *(float2*)(C + (size_t)(row + 8) * N + col) = make_float2(v2, v3);
        }
    }
}

// =================== aux kernels ============================================
__global__ void transpose_rn(const float* __restrict__ in, float* __restrict__ out,
                             int K, int N)
{
    __shared__ float t[32][33];
    const int n0 = blockIdx.x * 32, k0 = blockIdx.y * 32;
    const int x = threadIdx.x, y = threadIdx.y;
    for (int i = y; i < 32; i += 8)
        t[i][x] = in[(size_t)(k0 + i) * N + n0 + x];
    __syncthreads();
    for (int i = y; i < 32; i += 8)
        out[(size_t)(n0 + i) * K + k0 + x] = rn_tf32(t[x][i]);
}

__global__ void cvt_rn_vec(const float4* __restrict__ in, float4* __restrict__ out, int n4)
{
    int i = blockIdx.x * blockDim.x + threadIdx.x;
    if (i < n4) {
        float4 v = in[i];
        v.x = rn_tf32(v.x); v.y = rn_tf32(v.y); v.z = rn_tf32(v.z); v.w = rn_tf32(v.w);
        out[i] = v;
    }
}

// =================== tf32 mma flash attention ===============================
// grid (16, NH, Bc), 256 threads. BQ=128 queries/CTA, BK=64 keys/block.
#define BQ 128
#define BK 64
#define KPAD 132
#define VPAD 136
#define PPD  68
#define ATT_SMEM ((2*64*KPAD + 2*64*VPAD + BQ*PPD) * 4)   // 172032

__global__ __launch_bounds__(256, 1) void attn_mma()
{
    extern __shared__ float smf[];
    const uint32_t smb = smem_to_u32(smf);
    const int tid = threadIdx.x, wid = tid >> 5, lane = tid & 31;
    const int lr = lane >> 2, lc = lane & 3;
    const int qt = (int)(gridDim.x - 1 - blockIdx.x);   // heavy tiles first
    const int h = blockIdx.y, b = blockIdx.z, g = h >> 3;
    const int q0 = qt * BQ, m0 = wid * 16;

    const uint32_t offK0 = 0, offK1 = 64u*KPAD*4u;
    const uint32_t offV0 = 2u*64u*KPAD*4u, offV1 = offV0 + 64u*VPAD*4u;
    float* Ps = smf + 2*64*KPAD + 2*64*VPAD;

    // ---- persistent Q fragments (pre-scaled by 1/sqrt(D)*log2e, RN-rounded)
    const float cs = 0.12752191711633058f;
    uint32_t qf[16][4];
    {
        const float* q0p = g_qkv + ((size_t)(b*Tc + q0 + m0 + lr))*QKVW + h*DH;
        const float* q8p = q0p + (size_t)8*QKVW;
#pragma unroll
        for (int ks = 0; ks < 16; ks++) {
            qf[ks][0] = __float_as_uint(rn_tf32(q0p[ks*8+lc]   * cs));
            qf[ks][1] = __float_as_uint(rn_tf32(q8p[ks*8+lc]   * cs));
            qf[ks][2] = __float_as_uint(rn_tf32(q0p[ks*8+lc+4] * cs));
            qf[ks][3] = __float_as_uint(rn_tf32(q8p[ks*8+lc+4] * cs));
        }
    }

    float of[16][4];
#pragma unroll
    for (int i = 0; i < 16; i++)
#pragma unroll
        for (int r = 0; r < 4; r++) of[i][r] = 0.f;
    float mrow0 = -1e30f, mrow1 = -1e30f, lrow0 = 0.f, lrow1 = 0.f;

    const float* gK = g_qkv + (size_t)(b*Tc)*QKVW + 2048 + g*DH;
    const float* gV = gK + 256;
    const int nb = (q0 + BQ) / BK;

    // prologue fill (block 0 -> buf 0)
    {
#pragma unroll
        for (int n = 0; n < 8; n++) {
            int i = tid + n*256;
            int r = i >> 5, c = (i & 31) * 4;
            CP_ASYNC16(smb + offK0 + (uint32_t)(r*KPAD + c)*4u, gK + (size_t)r*QKVW + c);
            CP_ASYNC16(smb + offV0 + (uint32_t)(r*VPAD + c)*4u, gV + (size_t)r*QKVW + c);
        }
        CP_COMMIT;
    }

    for (int jt = 0; jt < nb; jt++) {
        const int buf = jt & 1;
        const int k0 = jt * BK;
        if (jt + 1 < nb) {
            const float* bk = gK + (size_t)((jt+1)*BK)*QKVW;
            const float* bv = gV + (size_t)((jt+1)*BK)*QKVW;
            const uint32_t oK = buf ? offK0 : offK1;
            const uint32_t oV = buf ? offV0 : offV1;
#pragma unroll
            for (int n = 0; n < 8; n++) {
                int i = tid + n*256;
                int r = i >> 5, c = (i & 31) * 4;
                CP_ASYNC16(smb + oK + (uint32_t)(r*KPAD + c)*4u, bk + (size_t)r*QKVW + c);
                CP_ASYNC16(smb + oV + (uint32_t)(r*VPAD + c)*4u, bv + (size_t)r*QKVW + c);
            }
        }
        CP_COMMIT;
        CP_WAIT1;
        __syncthreads();

        const float* Ks = smf + (buf ? offK1 : offK0) / 4;
        const float* Vs = smf + (buf ? offV1 : offV0) / 4;

        // ---- S = Q @ K^T (per warp: 16 x 64)
        float sf[8][4];
#pragma unroll
        for (int nf = 0; nf < 8; nf++)
#pragma unroll
            for (int r = 0; r < 4; r++) sf[nf][r] = 0.f;

#pragma unroll
        for (int nf = 0; nf < 8; nf++) {
            const float* kp = Ks + (nf*8 + lr)*KPAD + lc;
#pragma unroll
            for (int ks = 0; ks < 16; ks++) {
                uint32_t bfr[2] = { __float_as_uint(kp[ks*8]),
                                    __float_as_uint(kp[ks*8 + 4]) };
                mma_tf32(sf[nf], qf[ks], bfr);
            }
        }

        // ---- causal mask (only last two kv blocks can cross the diagonal)
        if (jt >= nb - 2) {
            const int row0 = q0 + m0 + lr, row1 = row0 + 8;
#pragma unroll
            for (int nf = 0; nf < 8; nf++) {
                const int col = k0 + nf*8 + lc*2;
                if (col     > row0) sf[nf][0] = -1e30f;
                if (col + 1 > row0) sf[nf][1] = -1e30f;
                if (col     > row1) sf[nf][2] = -1e30f;
                if (col + 1 > row1) sf[nf][3] = -1e30f;
            }
        }

        // ---- online softmax (log2 domain)
        float mx0 = mrow0, mx1 = mrow1;
#pragma unroll
        for (int nf = 0; nf < 8; nf++) {
            mx0 = fmaxf(mx0, fmaxf(sf[nf][0], sf[nf][1]));
            mx1 = fmaxf(mx1, fmaxf(sf[nf][2], sf[nf][3]));
        }
        mx0 = fmaxf(mx0, __shfl_xor_sync(0xffffffffu, mx0, 1, 4));
        mx0 = fmaxf(mx0, __shfl_xor_sync(0xffffffffu, mx0, 2, 4));
        mx1 = fmaxf(mx1, __shfl_xor_sync(0xffffffffu, mx1, 1, 4));
        mx1 = fmaxf(mx1, __shfl_xor_sync(0xffffffffu, mx1, 2, 4));
        const float alpha0 = ex2(mrow0 - mx0);
        const float alpha1 = ex2(mrow1 - mx1);
        mrow0 = mx0; mrow1 = mx1;

        float s0 = 0.f, s1 = 0.f;
#pragma unroll
        for (int nf = 0; nf < 8; nf++) {
            sf[nf][0] = ex2(sf[nf][0] - mx0);
            sf[nf][1] = ex2(sf[nf][1] - mx0);
            sf[nf][2] = ex2(sf[nf][2] - mx1);
            sf[nf][3] = ex2(sf[nf][3] - mx1);
            s0 += sf[nf][0] + sf[nf][1];
            s1 += sf[nf][2] + sf[nf][3];
        }
        s0 += __shfl_xor_sync(0xffffffffu, s0, 1, 4);
        s0 += __shfl_xor_sync(0xffffffffu, s0, 2, 4);
        s1 += __shfl_xor_sync(0xffffffffu, s1, 1, 4);
        s1 += __shfl_xor_sync(0xffffffffu, s1, 2, 4);
        lrow0 = lrow0 * alpha0 + s0;
        lrow1 = lrow1 * alpha1 + s1;

#pragma unroll
        for (int nf2 = 0; nf2 < 16; nf2++) {
            of[nf2][0] *= alpha0; of[nf2][1] *= alpha0;
            of[nf2][2] *= alpha1; of[nf2][3] *= alpha1;
        }

        // ---- store P (RN-rounded; warp-private rows)
#pragma unroll
        for (int nf = 0; nf < 8; nf++) {
            *(float2*)(Ps + (m0 + lr)    *PPD + nf*8 + lc*2) =
                make_float2(rn_tf32(sf[nf][0]), rn_tf32(sf[nf][1]));
            *(float2*)(Ps + (m0 + lr + 8)*PPD + nf*8 + lc*2) =
                make_float2(rn_tf32(sf[nf][2]), rn_tf32(sf[nf][3]));
        }
        __syncwarp();

        // ---- O += P @ V (per warp: 16 x 128)
#pragma unroll
        for (int ks2 = 0; ks2 < 8; ks2++) {
            uint32_t pf[4];
            pf[0] = __float_as_uint(Ps[(m0 + lr)    *PPD + ks2*8 + lc]);
            pf[1] = __float_as_uint(Ps[(m0 + lr + 8)*PPD + ks2*8 + lc]);
            pf[2] = __float_as_uint(Ps[(m0 + lr)    *PPD + ks2*8 + lc + 4]);
            pf[3] = __float_as_uint(Ps[(m0 + lr + 8)*PPD + ks2*8 + lc + 4]);
            const float* vp0 = Vs + (ks2*8 + lc)    *VPAD + lr;
            const float* vp1 = Vs + (ks2*8 + lc + 4)*VPAD + lr;
#pragma unroll
            for (int nf2 = 0; nf2 < 16; nf2++) {
                uint32_t vf[2] = { __float_as_uint(vp0[nf2*8]),
                                   __float_as_uint(vp1[nf2*8]) };
                mma_tf32(of[nf2], pf, vf);
            }
        }
        __syncthreads();
    }

    // ---- epilogue
    const float inv0 = 1.f / lrow0, inv1 = 1.f / lrow1;
    const int row0 = q0 + m0 + lr, row1 = row0 + 8;
#pragma unroll
    for (int nf2 = 0; nf2 < 16; nf2++) {
        const int col = h*DH + nf2*8 + lc*2;
        *(float2*)(g_yr + (size_t)(b*Tc + row0)*Cc + col) =
            make_float2(rn_tf32(of[nf2][0]*inv0), rn_tf32(of[nf2][1]*inv0));
        *(float2*)(g_yr + (size_t)(b*Tc + row1)*Cc + col) =
            make_float2(rn_tf32(of[nf2][2]*inv1), rn_tf32(of[nf2][3]*inv1));
    }
}

// =================== host side ==============================================
extern "C" void kernel_launch(void* const* d_in, const int* in_sizes, int n_in,
                              void* d_out, int out_size)
{
    const float* x  = (const float*)d_in[0];
    const float* Wq = (const float*)d_in[1];
    const float* Wk = (const float*)d_in[2];
    const float* Wv = (const float*)d_in[3];
    const float* Wo = (const float*)d_in[4];
    float* out = (float*)d_out;

    static bool inited = false;
    static float *xr, *qkvp, *yp, *wqkvt, *wot;
    if (!inited) {
        cudaGetSymbolAddress((void**)&xr,    g_xr);
        cudaGetSymbolAddress((void**)&qkvp,  g_qkv);
        cudaGetSymbolAddress((void**)&yp,    g_yr);
        cudaGetSymbolAddress((void**)&wqkvt, g_wqkvt);
        cudaGetSymbolAddress((void**)&wot,   g_wot);
        cudaFuncSetAttribute(attn_mma, cudaFuncAttributeMaxDynamicSharedMemorySize,
                             ATT_SMEM);
        inited = true;
    }

    // 1) RN-round x
    cvt_rn_vec<<<(Mrows * Cc / 4 + 255) / 256, 256>>>((const float4*)x, (float4*)xr,
                                                      Mrows * Cc / 4);
    // 2) transpose + RN-round weights into fused [Wq^T;Wk^T;Wv^T] and Wo^T
    dim3 tb(32, 8);
    transpose_rn<<<dim3(Cc / 32,  Cc / 32), tb>>>(Wq, wqkvt,                         Cc, Cc);
    transpose_rn<<<dim3(256 / 32, Cc / 32), tb>>>(Wk, wqkvt + (size_t)2048 * Cc,     Cc, 256);
    transpose_rn<<<dim3(256 / 32, Cc / 32), tb>>>(Wv, wqkvt + (size_t)2304 * Cc,     Cc, 256);
    transpose_rn<<<dim3(Cc / 32,  Cc / 32), tb>>>(Wo, wot, Cc, Cc);

    // 3) fused QKV projection (rounded epilogue feeds attention)
    gemm_mma<<<dim3(QKVW / 128, Mrows / 128), 256>>>(xr, wqkvt, qkvp,
                                                     Mrows, QKVW, Cc, 1);
    // 4) attention (tf32 mma flash)
    attn_mma<<<dim3(Tc / BQ, NH, Bc), 256, ATT_SMEM>>>();

    // 5) output projection
    gemm_mma<<<dim3(Cc / 128, Mrows / 128), 256>>>(yp, wot, out, Mrows, Cc, Cc, 0);
}

// round 5
// speedup vs baseline: 8.2557x; 1.8963x over previous
#include <cuda_runtime.h>
#include <cuda_fp16.h>
#include <cstdint>

#define Bc   2
#define Tc   2048
#define Cc   2048
#define NH   16
#define NKV  2
#define DH   128
#define Mrows (Bc*Tc)          // 4096
#define QKVW 2560              // q(2048) | k(256) | v(256)

// ---------------- scratch (allocation-free rule: __device__ globals) --------
__device__ __half g_xh  [(size_t)Mrows * Cc];     // fp16 x
__device__ __half g_qkv [(size_t)Mrows * QKVW];   // fused projections (fp16)
__device__ __half g_yh  [(size_t)Mrows * Cc];     // attention out (fp16)
__device__ __half g_wqkvt[(size_t)QKVW * Cc];     // [Wq^T ; Wk^T ; Wv^T] fp16
__device__ __half g_wot [(size_t)Cc * Cc];        // Wo^T fp16

__device__ __forceinline__ float ex2(float x) {
    float y; asm("ex2.approx.f32 %0, %1;" : "=f"(y) : "f"(x)); return y;
}
__device__ __forceinline__ uint32_t smem_to_u32(const void* p) {
    uint32_t a;
    asm("{ .reg .u64 t; cvta.to.shared.u64 t, %1; cvt.u32.u64 %0, t; }"
        : "=r"(a) : "l"(p));
    return a;
}
__device__ __forceinline__ uint32_t pack_h2(float lo, float hi) {
    __half2 h = __floats2half2_rn(lo, hi);
    return *(uint32_t*)&h;
}
__device__ __forceinline__ void mma_f16(float* c, const uint32_t* a, const uint32_t* b) {
    asm volatile(
        "mma.sync.aligned.m16n8k16.row.col.f32.f16.f16.f32 "
        "{%0,%1,%2,%3}, {%4,%5,%6,%7}, {%8,%9}, {%0,%1,%2,%3};"
        : "+f"(c[0]), "+f"(c[1]), "+f"(c[2]), "+f"(c[3])
        : "r"(a[0]), "r"(a[1]), "r"(a[2]), "r"(a[3]), "r"(b[0]), "r"(b[1]));
}
#define LDMATRIX_X4_TRANS(r0, r1, r2, r3, addr) \
    asm volatile("ldmatrix.sync.aligned.m8n8.x4.trans.shared.b16 {%0,%1,%2,%3}, [%4];" \
        : "=r"(r0), "=r"(r1), "=r"(r2), "=r"(r3) : "r"(addr))
#define CP_ASYNC16(sm, gp) \
    asm volatile("cp.async.cg.shared.global [%0], [%1], 16;" :: "r"(sm), "l"(gp))
#define CP_COMMIT asm volatile("cp.async.commit_group;" ::: "memory")
#define CP_WAIT1  asm volatile("cp.async.wait_group 1;"  ::: "memory")

// =================== fp16 mma GEMM ==========================================
// C[M,N] = A[M,K] @ Bt[N,K]^T. A,Bt fp16 row-major. out_half: fp16 C, else fp32.
#define KCG 32      // K-chunk in halves
#define KPG 40      // smem row stride (halves): 20*row+lc bank pattern, conflict-free

__global__ __launch_bounds__(256) void gemm_hmma(const __half* __restrict__ A,
                                                 const __half* __restrict__ Bt,
                                                 float* __restrict__ Cf,
                                                 __half* __restrict__ Ch,
                                                 int M, int N, int K, int out_half)
{
    __shared__ __half As[2][128 * KPG];
    __shared__ __half Bs[2][128 * KPG];

    const int tid  = threadIdx.x;
    const int wid  = tid >> 5, lane = tid & 31;
    const int lr   = lane >> 2, lc = lane & 3;
    const int wm   = (wid & 1) * 64;
    const int wn   = (wid >> 1) * 32;
    const int bm   = blockIdx.y * 128;
    const int bn   = blockIdx.x * 128;

    // tile fill: 512 x 16B per tile, 2 per thread (rows r0, r0+64; col c8 halves)
    const int r0 = tid >> 2, c8 = (tid & 3) * 8;
    const int r1 = r0 + 64;

    float acc[4][4][4];
#pragma unroll
    for (int i = 0; i < 4; i++)
#pragma unroll
        for (int j = 0; j < 4; j++)
#pragma unroll
            for (int r = 0; r < 4; r++) acc[i][j][r] = 0.f;

    const int nc = K / KCG;

    float4 pa0 = *(const float4*)(A  + (size_t)(bm + r0) * K + c8);
    float4 pa1 = *(const float4*)(A  + (size_t)(bm + r1) * K + c8);
    float4 pb0 = *(const float4*)(Bt + (size_t)(bn + r0) * K + c8);
    float4 pb1 = *(const float4*)(Bt + (size_t)(bn + r1) * K + c8);
    *(float4*)(&As[0][r0 * KPG + c8]) = pa0;
    *(float4*)(&As[0][r1 * KPG + c8]) = pa1;
    *(float4*)(&Bs[0][r0 * KPG + c8]) = pb0;
    *(float4*)(&Bs[0][r1 * KPG + c8]) = pb1;
    __syncthreads();

    for (int c = 0; c < nc; c++) {
        const int buf = c & 1;
        if (c + 1 < nc) {
            const int kb = (c + 1) * KCG;
            pa0 = *(const float4*)(A  + (size_t)(bm + r0) * K + kb + c8);
            pa1 = *(const float4*)(A  + (size_t)(bm + r1) * K + kb + c8);
            pb0 = *(const float4*)(Bt + (size_t)(bn + r0) * K + kb + c8);
            pb1 = *(const float4*)(Bt + (size_t)(bn + r1) * K + kb + c8);
        }

#pragma unroll
        for (int ks = 0; ks < 2; ks++) {
            const int k0 = ks * 16;
            uint32_t af[4][4], bf[4][2];
#pragma unroll
            for (int mf = 0; mf < 4; mf++) {
                const __half* p0 = &As[buf][(wm + mf*16 + lr) * KPG + k0 + 2*lc];
                af[mf][0] = *(const uint32_t*)(p0);
                af[mf][1] = *(const uint32_t*)(p0 + 8 * KPG);
                af[mf][2] = *(const uint32_t*)(p0 + 8);
                af[mf][3] = *(const uint32_t*)(p0 + 8 * KPG + 8);
            }
#pragma unroll
            for (int nf = 0; nf < 4; nf++) {
                const __half* p0 = &Bs[buf][(wn + nf*8 + lr) * KPG + k0 + 2*lc];
                bf[nf][0] = *(const uint32_t*)(p0);
                bf[nf][1] = *(const uint32_t*)(p0 + 8);
            }
#pragma unroll
            for (int mf = 0; mf < 4; mf++)
#pragma unroll
                for (int nf = 0; nf < 4; nf++)
                    mma_f16(acc[mf][nf], af[mf], bf[nf]);
        }

        if (c + 1 < nc) {
            const int nb = buf ^ 1;
            *(float4*)(&As[nb][r0 * KPG + c8]) = pa0;
            *(float4*)(&As[nb][r1 * KPG + c8]) = pa1;
            *(float4*)(&Bs[nb][r0 * KPG + c8]) = pb0;
            *(float4*)(&Bs[nb][r1 * KPG + c8]) = pb1;
        }
        __syncthreads();
    }

#pragma unroll
    for (int mf = 0; mf < 4; mf++) {
#pragma unroll
        for (int nf = 0; nf < 4; nf++) {
            const int row = bm + wm + mf * 16 + lr;
            const int col = bn + wn + nf * 8 + lc * 2;
            if (out_half) {
                *(uint32_t*)(Ch + (size_t)row * N + col) =
                    pack_h2(acc[mf][nf][0], acc[mf][nf][1]);
                *(uint32_t*)(Ch + (size_t)(row + 8) * N + col) =
                    pack_h2(acc[mf][nf][2], acc[mf][nf][3]);
            } else {
                *(float2*)(Cf + (size_t)row * N + col) =
                    make_float2(acc[mf][nf][0], acc[mf][nf][1]);
                *(float2*)(Cf + (size_t)(row + 8) * N + col) =
                    make_float2(acc[mf][nf][2], acc[mf][nf][3]);
            }
        }
    }
}

// =================== aux kernels ============================================
// out[n][k] = half(in[k][n]); in fp32 [K][N] row-major, out fp16 [N][K].
__global__ void transpose_h(const float* __restrict__ in, __half* __restrict__ out,
                            int K, int N)
{
    __shared__ float t[32][33];
    const int n0 = blockIdx.x * 32, k0 = blockIdx.y * 32;
    const int x = threadIdx.x, y = threadIdx.y;
    for (int i = y; i < 32; i += 8)
        t[i][x] = in[(size_t)(k0 + i) * N + n0 + x];
    __syncthreads();
    for (int i = y; i < 32; i += 8)
        out[(size_t)(n0 + i) * K + k0 + x] = __float2half_rn(t[x][i]);
}

__global__ void cvt_h_vec(const float4* __restrict__ in, __half2* __restrict__ out, int n4)
{
    int i = blockIdx.x * blockDim.x + threadIdx.x;
    if (i < n4) {
        float4 v = in[i];
        out[2*i]   = __floats2half2_rn(v.x, v.y);
        out[2*i+1] = __floats2half2_rn(v.z, v.w);
    }
}

// =================== fp16 mma flash attention ===============================
// grid (16, NH, Bc), 256 threads. BQ=128 queries/CTA, BK=64 keys/block.
#define BQ 128
#define BK 64
#define KPH 136                 // K/V smem row stride in halves (272 B)
#define ATT_SMEM (4 * 64 * KPH * 2)   // 2 bufs x (K + V) = 69632 B

__global__ __launch_bounds__(256, 1) void attn_hmma()
{
    extern __shared__ __half smh[];
    const uint32_t smb = smem_to_u32(smh);
    const int tid = threadIdx.x, wid = tid >> 5, lane = tid & 31;
    const int lr = lane >> 2, lc = lane & 3;
    const int qt = (int)(gridDim.x - 1 - blockIdx.x);   // heavy tiles first
    const int h = blockIdx.y, b = blockIdx.z, g = h >> 3;
    const int q0 = qt * BQ, m0 = wid * 16;

    const uint32_t offK0 = 0,                offK1 = 64u*KPH*2u;
    const uint32_t offV0 = 2u*64u*KPH*2u,    offV1 = offV0 + 64u*KPH*2u;

    // ---- persistent Q fragments (raw fp16; softmax scale applied to S)
    uint32_t qf[8][4];
    {
        const __half* q0p = g_qkv + ((size_t)(b*Tc + q0 + m0 + lr))*QKVW + h*DH;
        const __half* q8p = q0p + (size_t)8*QKVW;
#pragma unroll
        for (int ks = 0; ks < 8; ks++) {
            qf[ks][0] = *(const uint32_t*)(q0p + ks*16 + 2*lc);
            qf[ks][1] = *(const uint32_t*)(q8p + ks*16 + 2*lc);
            qf[ks][2] = *(const uint32_t*)(q0p + ks*16 + 2*lc + 8);
            qf[ks][3] = *(const uint32_t*)(q8p + ks*16 + 2*lc + 8);
        }
    }

    float of[16][4];
#pragma unroll
    for (int i = 0; i < 16; i++)
#pragma unroll
        for (int r = 0; r < 4; r++) of[i][r] = 0.f;
    float mrow0 = -1e30f, mrow1 = -1e30f, lrow0 = 0.f, lrow1 = 0.f;
    const float cs = 0.12752191711633058f;   // log2(e)/sqrt(128)

    const __half* gK = g_qkv + (size_t)(b*Tc)*QKVW + 2048 + g*DH;
    const __half* gV = gK + 256;
    const int nb = (q0 + BQ) / BK;

    // fill mapping: 64 rows x 128 halves = 1024 x 16B, 4 per thread per tile
    const int fr = tid >> 2, fc = (tid & 3) * 32;   // 4 rows-chunks? no:
    // i = tid + n*256 -> r = i>>4, c16 = (i&15)*8
    {
#pragma unroll
        for (int n = 0; n < 4; n++) {
            int i = tid + n*256;
            int r = i >> 4, c = (i & 15) * 8;
            CP_ASYNC16(smb + offK0 + (uint32_t)(r*KPH + c)*2u, gK + (size_t)r*QKVW + c);
            CP_ASYNC16(smb + offV0 + (uint32_t)(r*KPH + c)*2u, gV + (size_t)r*QKVW + c);
        }
        CP_COMMIT;
    }
    (void)fr; (void)fc;

    for (int jt = 0; jt < nb; jt++) {
        const int buf = jt & 1;
        const int k0 = jt * BK;
        if (jt + 1 < nb) {
            const __half* bk = gK + (size_t)((jt+1)*BK)*QKVW;
            const __half* bv = gV + (size_t)((jt+1)*BK)*QKVW;
            const uint32_t oK = buf ? offK0 : offK1;
            const uint32_t oV = buf ? offV0 : offV1;
#pragma unroll
            for (int n = 0; n < 4; n++) {
                int i = tid + n*256;
                int r = i >> 4, c = (i & 15) * 8;
                CP_ASYNC16(smb + oK + (uint32_t)(r*KPH + c)*2u, bk + (size_t)r*QKVW + c);
                CP_ASYNC16(smb + oV + (uint32_t)(r*KPH + c)*2u, bv + (size_t)r*QKVW + c);
            }
        }
        CP_COMMIT;
        CP_WAIT1;
        __syncthreads();

        const __half* Ks = smh + (buf ? offK1 : offK0) / 2;
        const uint32_t Vb = smb + (buf ? offV1 : offV0);

        // ---- S = Q @ K^T (per warp: 16 x 64)
        float sf[8][4];
#pragma unroll
        for (int nf = 0; nf < 8; nf++)
#pragma unroll
            for (int r = 0; r < 4; r++) sf[nf][r] = 0.f;

#pragma unroll
        for (int nf = 0; nf < 8; nf++) {
            const __half* kp = Ks + (nf*8 + lr)*KPH + 2*lc;
#pragma unroll
            for (int ks = 0; ks < 8; ks++) {
                uint32_t bfr[2] = { *(const uint32_t*)(kp + ks*16),
                                    *(const uint32_t*)(kp + ks*16 + 8) };
                mma_f16(sf[nf], qf[ks], bfr);
            }
        }

        // scale (exact fp32) then causal mask
#pragma unroll
        for (int nf = 0; nf < 8; nf++) {
            sf[nf][0] *= cs; sf[nf][1] *= cs; sf[nf][2] *= cs; sf[nf][3] *= cs;
        }
        if (jt >= nb - 2) {
            const int row0 = q0 + m0 + lr, row1 = row0 + 8;
#pragma unroll
            for (int nf = 0; nf < 8; nf++) {
                const int col = k0 + nf*8 + lc*2;
                if (col     > row0) sf[nf][0] = -1e30f;
                if (col + 1 > row0) sf[nf][1] = -1e30f;
                if (col     > row1) sf[nf][2] = -1e30f;
                if (col + 1 > row1) sf[nf][3] = -1e30f;
            }
        }

        // ---- online softmax (log2 domain)
        float mx0 = mrow0, mx1 = mrow1;
#pragma unroll
        for (int nf = 0; nf < 8; nf++) {
            mx0 = fmaxf(mx0, fmaxf(sf[nf][0], sf[nf][1]));
            mx1 = fmaxf(mx1, fmaxf(sf[nf][2], sf[nf][3]));
        }
        mx0 = fmaxf(mx0, __shfl_xor_sync(0xffffffffu, mx0, 1, 4));
        mx0 = fmaxf(mx0, __shfl_xor_sync(0xffffffffu, mx0, 2, 4));
        mx1 = fmaxf(mx1, __shfl_xor_sync(0xffffffffu, mx1, 1, 4));
        mx1 = fmaxf(mx1, __shfl_xor_sync(0xffffffffu, mx1, 2, 4));
        const float alpha0 = ex2(mrow0 - mx0);
        const float alpha1 = ex2(mrow1 - mx1);
        mrow0 = mx0; mrow1 = mx1;

        float s0 = 0.f, s1 = 0.f;
#pragma unroll
        for (int nf = 0; nf < 8; nf++) {
            sf[nf][0] = ex2(sf[nf][0] - mx0);
            sf[nf][1] = ex2(sf[nf][1] - mx0);
            sf[nf][2] = ex2(sf[nf][2] - mx1);
            sf[nf][3] = ex2(sf[nf][3] - mx1);
            s0 += sf[nf][0] + sf[nf][1];
            s1 += sf[nf][2] + sf[nf][3];
        }
        s0 += __shfl_xor_sync(0xffffffffu, s0, 1, 4);
        s0 += __shfl_xor_sync(0xffffffffu, s0, 2, 4);
        s1 += __shfl_xor_sync(0xffffffffu, s1, 1, 4);
        s1 += __shfl_xor_sync(0xffffffffu, s1, 2, 4);
        lrow0 = lrow0 * alpha0 + s0;
        lrow1 = lrow1 * alpha1 + s1;

#pragma unroll
        for (int nf2 = 0; nf2 < 16; nf2++) {
            of[nf2][0] *= alpha0; of[nf2][1] *= alpha0;
            of[nf2][2] *= alpha1; of[nf2][3] *= alpha1;
        }

        // ---- O += P @ V; P built in-register from S frags (no smem round-trip)
#pragma unroll
        for (int ks2 = 0; ks2 < 4; ks2++) {
            uint32_t pf[4];
            pf[0] = pack_h2(sf[2*ks2][0],   sf[2*ks2][1]);
            pf[1] = pack_h2(sf[2*ks2][2],   sf[2*ks2][3]);
            pf[2] = pack_h2(sf[2*ks2+1][0], sf[2*ks2+1][1]);
            pf[3] = pack_h2(sf[2*ks2+1][2], sf[2*ks2+1][3]);
            const uint32_t vrow = (uint32_t)(ks2*16 + (lane & 15));
#pragma unroll
            for (int np = 0; np < 8; np++) {
                const uint32_t vaddr = Vb +
                    (vrow * KPH + (uint32_t)(np*16 + (lane >> 4) * 8)) * 2u;
                uint32_t v0, v1, v2, v3;
                LDMATRIX_X4_TRANS(v0, v1, v2, v3, vaddr);
                uint32_t vf0[2] = {v0, v1}, vf1[2] = {v2, v3};
                mma_f16(of[2*np],   pf, vf0);
                mma_f16(of[2*np+1], pf, vf1);
            }
        }
        __syncthreads();
    }

    // ---- epilogue (fp16 out)
    const float inv0 = 1.f / lrow0, inv1 = 1.f / lrow1;
    const int row0 = q0 + m0 + lr, row1 = row0 + 8;
#pragma unroll
    for (int nf2 = 0; nf2 < 16; nf2++) {
        const int col = h*DH + nf2*8 + lc*2;
        *(uint32_t*)(g_yh + (size_t)(b*Tc + row0)*Cc + col) =
            pack_h2(of[nf2][0]*inv0, of[nf2][1]*inv0);
        *(uint32_t*)(g_yh + (size_t)(b*Tc + row1)*Cc + col) =
            pack_h2(of[nf2][2]*inv1, of[nf2][3]*inv1);
    }
}

// =================== host side ==============================================
extern "C" void kernel_launch(void* const* d_in, const int* in_sizes, int n_in,
                              void* d_out, int out_size)
{
    const float* x  = (const float*)d_in[0];
    const float* Wq = (const float*)d_in[1];
    const float* Wk = (const float*)d_in[2];
    const float* Wv = (const float*)d_in[3];
    const float* Wo = (const float*)d_in[4];
    float* out = (float*)d_out;

    static bool inited = false;
    static __half *xh, *qkvp, *yh, *wqkvt, *wot;
    if (!inited) {
        cudaGetSymbolAddress((void**)&xh,    g_xh);
        cudaGetSymbolAddress((void**)&qkvp,  g_qkv);
        cudaGetSymbolAddress((void**)&yh,    g_yh);
        cudaGetSymbolAddress((void**)&wqkvt, g_wqkvt);
        cudaGetSymbolAddress((void**)&wot,   g_wot);
        cudaFuncSetAttribute(attn_hmma, cudaFuncAttributeMaxDynamicSharedMemorySize,
                             ATT_SMEM);
        inited = true;
    }

    // 1) x -> fp16
    cvt_h_vec<<<(Mrows * Cc / 4 + 255) / 256, 256>>>((const float4*)x, (__half2*)xh,
                                                     Mrows * Cc / 4);
    // 2) transpose weights -> fp16 [Wq^T;Wk^T;Wv^T] and Wo^T
    dim3 tb(32, 8);
    transpose_h<<<dim3(Cc / 32,  Cc / 32), tb>>>(Wq, wqkvt,                     Cc, Cc);
    transpose_h<<<dim3(256 / 32, Cc / 32), tb>>>(Wk, wqkvt + (size_t)2048 * Cc, Cc, 256);
    transpose_h<<<dim3(256 / 32, Cc / 32), tb>>>(Wv, wqkvt + (size_t)2304 * Cc, Cc, 256);
    transpose_h<<<dim3(Cc / 32,  Cc / 32), tb>>>(Wo, wot, Cc, Cc);

    // 3) fused QKV projection (fp16 out)
    gemm_hmma<<<dim3(QKVW / 128, Mrows / 128), 256>>>(xh, wqkvt, nullptr, qkvp,
                                                      Mrows, QKVW, Cc, 1);
    // 4) attention (fp16 mma flash)
    attn_hmma<<<dim3(Tc / BQ, NH, Bc), 256, ATT_SMEM>>>();

    // 5) output projection (fp32 out)
    gemm_hmma<<<dim3(Cc / 128, Mrows / 128), 256>>>(yh, wot, out, nullptr,
                                                    Mrows, Cc, Cc, 0);
}